// round 3
// baseline (speedup 1.0000x reference)
#include <cuda_runtime.h>
#include <math.h>
#include <stdint.h>

#define T_SEQ 4096
#define C_DIM 2048
#define KV_DIM 512
#define QKV_N 3072
#define NH 16
#define NKV 4
#define HD 128
#define HALF 64
#define WIN 64

// Scratch (no runtime allocation allowed)
__device__ float g_Q[T_SEQ * C_DIM];
__device__ float g_K[T_SEQ * KV_DIM];
__device__ float g_V[T_SEQ * KV_DIM];
__device__ float g_AO[T_SEQ * C_DIM];
__device__ float g_XR[T_SEQ * C_DIM];          // tf32-rounded x
__device__ float g_W[C_DIM * QKV_N];           // tf32-rounded [wq|wk|wv]
__device__ float g_WO[C_DIM * C_DIM];          // tf32-rounded wo

__device__ __forceinline__ uint32_t f2tf32(float f) {
    uint32_t u;
    asm("cvt.rna.tf32.f32 %0, %1;" : "=r"(u) : "f"(f));
    return u;
}
__device__ __forceinline__ float rna(float f) { return __uint_as_float(f2tf32(f)); }

// ---------------------------------------------------------------------------
// Elementwise tf32 rounding passes
// ---------------------------------------------------------------------------
__global__ void round_copy4(const float4* __restrict__ src, float4* __restrict__ dst,
                            int n4) {
    int i = blockIdx.x * blockDim.x + threadIdx.x;
    if (i >= n4) return;
    float4 v = src[i];
    dst[i] = make_float4(rna(v.x), rna(v.y), rna(v.z), rna(v.w));
}

__global__ void build_w(const float4* __restrict__ wq, const float4* __restrict__ wk,
                        const float4* __restrict__ wv, float4* __restrict__ W) {
    int i = blockIdx.x * blockDim.x + threadIdx.x;   // over C_DIM*QKV_N/4
    if (i >= C_DIM * QKV_N / 4) return;
    int c4 = i % (QKV_N / 4);
    int k  = i / (QKV_N / 4);
    int col = c4 * 4;
    float4 v;
    if (col < C_DIM)            v = wq[(k * C_DIM + col) >> 2];
    else if (col < C_DIM + KV_DIM) v = wk[(k * KV_DIM + col - C_DIM) >> 2];
    else                        v = wv[(k * KV_DIM + col - C_DIM - KV_DIM) >> 2];
    W[i] = make_float4(rna(v.x), rna(v.y), rna(v.z), rna(v.w));
}

// ---------------------------------------------------------------------------
// TF32 tensor-core GEMM, cp.async 4-stage pipeline.
// C[M,N] = A[M,K] @ B[K,N], row-major, inputs already tf32-rounded fp32.
// 128x128x32 tiles, 256 threads, warp tile 64x32, mma.m16n8k8.
// mode 0: plain store. mode 1: QKV epilogue (rope + route to g_Q/g_K/g_V).
// ---------------------------------------------------------------------------
#define STAGES 4
#define SA 36
#define SB 132
#define STG_FLOATS (128 * SA + 32 * SB)   // 8832 floats = 35328 B

__device__ __forceinline__ void cp16(uint32_t dst, const float* src) {
    asm volatile("cp.async.ca.shared.global [%0], [%1], 16;\n" :: "r"(dst), "l"(src));
}

__device__ __forceinline__ void mma_tf32(float c[4], const uint32_t a[4],
                                         const uint32_t b[2]) {
    asm volatile(
        "mma.sync.aligned.m16n8k8.row.col.f32.tf32.tf32.f32 "
        "{%0,%1,%2,%3}, {%4,%5,%6,%7}, {%8,%9}, {%0,%1,%2,%3};\n"
        : "+f"(c[0]), "+f"(c[1]), "+f"(c[2]), "+f"(c[3])
        : "r"(a[0]), "r"(a[1]), "r"(a[2]), "r"(a[3]), "r"(b[0]), "r"(b[1]));
}

__device__ __forceinline__ void issue_stage(const float* __restrict__ A,
                                            const float* __restrict__ B, int kt,
                                            uint32_t smem_u, int bm, int bn,
                                            int arow, int acol, int brow, int bcol,
                                            int K, int N) {
    uint32_t base = smem_u + (uint32_t)(kt & (STAGES - 1)) * (STG_FLOATS * 4);
    const float* Ab = A + (size_t)kt * 32 + (size_t)(bm + arow) * K + acol;
#pragma unroll
    for (int p = 0; p < 4; p++)
        cp16(base + ((arow + p * 32) * SA + acol) * 4, Ab + (size_t)p * 32 * K);
    const float* Bb = B + ((size_t)kt * 32 + brow) * N + bn + bcol;
    uint32_t bb = base + 128 * SA * 4;
#pragma unroll
    for (int p = 0; p < 4; p++)
        cp16(bb + ((brow + p * 8) * SB + bcol) * 4, Bb + (size_t)p * 8 * N);
    asm volatile("cp.async.commit_group;\n" ::);
}

__device__ __forceinline__ void qkv_store(int t, int col, float v0, float v1) {
    if (col < C_DIM) {
        int jj = (col & 127) >> 1;
        float invf = powf(10000.f, -(float)jj * (1.f / 64.f));
        float s, c;
        sincosf((float)t * invf, &s, &c);
        *(float2*)&g_Q[(size_t)t * C_DIM + col] =
            make_float2(v0 * c - v1 * s, v0 * s + v1 * c);
    } else if (col < C_DIM + KV_DIM) {
        int kc = col - C_DIM;
        int jj = (kc & 127) >> 1;
        float invf = powf(10000.f, -(float)jj * (1.f / 64.f));
        float s, c;
        sincosf((float)t * invf, &s, &c);
        *(float2*)&g_K[(size_t)t * KV_DIM + kc] =
            make_float2(v0 * c - v1 * s, v0 * s + v1 * c);
    } else {
        int vc = col - C_DIM - KV_DIM;
        *(float2*)&g_V[(size_t)t * KV_DIM + vc] = make_float2(v0, v1);
    }
}

__global__ void __launch_bounds__(256, 1) gemm_tf32(const float* __restrict__ A,
                                                    const float* __restrict__ B,
                                                    float* __restrict__ C,
                                                    int M, int N, int K, int mode) {
    extern __shared__ float smem[];
    uint32_t smem_u;
    asm("{.reg .u64 t; cvta.to.shared.u64 t, %1; cvt.u32.u64 %0, t;}"
        : "=r"(smem_u) : "l"(smem));

    const int tid = threadIdx.x;
    const int bm = blockIdx.y * 128;
    const int bn = blockIdx.x * 128;
    const int warp = tid >> 5;
    const int lane = tid & 31;
    const int wm = warp >> 2;
    const int wn = warp & 3;
    const int g  = lane >> 2;
    const int tg = lane & 3;

    const int arow = tid >> 3;
    const int acol = (tid & 7) << 2;
    const int brow = tid >> 5;
    const int bcol = (tid & 31) << 2;

    const int KT = K >> 5;

    float acc[4][4][4];
#pragma unroll
    for (int i = 0; i < 4; i++)
#pragma unroll
        for (int j = 0; j < 4; j++)
#pragma unroll
            for (int r = 0; r < 4; r++) acc[i][j][r] = 0.f;

#pragma unroll
    for (int s = 0; s < STAGES - 1; s++)
        if (s < KT)
            issue_stage(A, B, s, smem_u, bm, bn, arow, acol, brow, bcol, K, N);

    for (int kt = 0; kt < KT; kt++) {
        asm volatile("cp.async.wait_group %0;\n" :: "n"(STAGES - 2));
        __syncthreads();

        if (kt + STAGES - 1 < KT)
            issue_stage(A, B, kt + STAGES - 1, smem_u, bm, bn, arow, acol, brow,
                        bcol, K, N);

        const uint32_t* su =
            (const uint32_t*)(smem + (size_t)(kt & (STAGES - 1)) * STG_FLOATS);
        const uint32_t* bu = su + 128 * SA;

#pragma unroll
        for (int ks = 0; ks < 4; ks++) {
            const int kk = ks * 8 + tg;
            uint32_t af[4][4], bf[4][2];
#pragma unroll
            for (int i = 0; i < 4; i++) {
                int r0 = (wm * 64 + i * 16 + g) * SA;
                af[i][0] = su[r0 + kk];
                af[i][1] = su[r0 + 8 * SA + kk];
                af[i][2] = su[r0 + kk + 4];
                af[i][3] = su[r0 + 8 * SA + kk + 4];
            }
#pragma unroll
            for (int j = 0; j < 4; j++) {
                int c0 = wn * 32 + j * 8 + g;
                bf[j][0] = bu[kk * SB + c0];
                bf[j][1] = bu[(kk + 4) * SB + c0];
            }
#pragma unroll
            for (int i = 0; i < 4; i++)
#pragma unroll
                for (int j = 0; j < 4; j++) mma_tf32(acc[i][j], af[i], bf[j]);
        }
    }

    if (mode == 0) {
#pragma unroll
        for (int i = 0; i < 4; i++)
#pragma unroll
            for (int j = 0; j < 4; j++) {
                int row = bm + wm * 64 + i * 16 + g;
                int col = bn + wn * 32 + j * 8 + 2 * tg;
                *(float2*)(C + (size_t)row * N + col) =
                    make_float2(acc[i][j][0], acc[i][j][1]);
                *(float2*)(C + (size_t)(row + 8) * N + col) =
                    make_float2(acc[i][j][2], acc[i][j][3]);
            }
    } else {
#pragma unroll
        for (int i = 0; i < 4; i++)
#pragma unroll
            for (int j = 0; j < 4; j++) {
                int row = bm + wm * 64 + i * 16 + g;
                int col = bn + wn * 32 + j * 8 + 2 * tg;
                qkv_store(row, col, acc[i][j][0], acc[i][j][1]);
                qkv_store(row + 8, col, acc[i][j][2], acc[i][j][3]);
            }
    }
}

// ---------------------------------------------------------------------------
// Sliding-window attention: one warp handles 4 adjacent queries of one head,
// sharing each K/V float4 load. Branchy online softmax. sink cancels; ignored.
// Output is tf32-rounded (feeds final GEMM directly).
// ---------------------------------------------------------------------------
__global__ void __launch_bounds__(256) attn_kernel(const float* __restrict__ Q,
                                                   const float* __restrict__ K,
                                                   const float* __restrict__ V,
                                                   float* __restrict__ O) {
    const int warp = threadIdx.x >> 5;
    const int lane = threadIdx.x & 31;
    const int tq = (blockIdx.x * 8 + warp) * 4;
    const int h = blockIdx.y;
    const int kh = h >> 2;
    const float scale = 0.08838834764831845f;

    float4 q[4];
#pragma unroll
    for (int i = 0; i < 4; i++)
        q[i] = *(const float4*)(Q + (size_t)(tq + i) * C_DIM + h * HD + lane * 4);

    float m[4] = {-1e30f, -1e30f, -1e30f, -1e30f};
    float l[4] = {0.f, 0.f, 0.f, 0.f};
    float4 a[4];
#pragma unroll
    for (int i = 0; i < 4; i++) a[i] = make_float4(0.f, 0.f, 0.f, 0.f);

    int s0 = tq - WIN;      if (s0 < 0) s0 = 0;
    int s1 = tq + 3 + WIN;  if (s1 > T_SEQ - 1) s1 = T_SEQ - 1;

    for (int s = s0; s <= s1; s++) {
        float4 kv = *(const float4*)(K + (size_t)s * KV_DIM + kh * HD + lane * 4);
        float4 vv = *(const float4*)(V + (size_t)s * KV_DIM + kh * HD + lane * 4);
#pragma unroll
        for (int i = 0; i < 4; i++) {
            int t = tq + i;
            if (s < t - WIN || s > t + WIN) continue;  // warp-uniform
            float d = q[i].x * kv.x + q[i].y * kv.y + q[i].z * kv.z + q[i].w * kv.w;
#pragma unroll
            for (int o = 16; o > 0; o >>= 1) d += __shfl_xor_sync(0xffffffffu, d, o);
            d *= scale;
            if (d <= m[i]) {
                float p = __expf(d - m[i]);
                l[i] += p;
                a[i].x += p * vv.x;
                a[i].y += p * vv.y;
                a[i].z += p * vv.z;
                a[i].w += p * vv.w;
            } else {
                float corr = __expf(m[i] - d);
                m[i] = d;
                l[i] = l[i] * corr + 1.f;
                a[i].x = a[i].x * corr + vv.x;
                a[i].y = a[i].y * corr + vv.y;
                a[i].z = a[i].z * corr + vv.z;
                a[i].w = a[i].w * corr + vv.w;
            }
        }
    }
#pragma unroll
    for (int i = 0; i < 4; i++) {
        float inv = 1.f / l[i];
        *(float4*)(O + (size_t)(tq + i) * C_DIM + h * HD + lane * 4) =
            make_float4(rna(a[i].x * inv), rna(a[i].y * inv),
                        rna(a[i].z * inv), rna(a[i].w * inv));
    }
}

// ---------------------------------------------------------------------------
extern "C" void kernel_launch(void* const* d_in, const int* in_sizes, int n_in,
                              void* d_out, int out_size) {
    const float* x  = (const float*)d_in[0];
    const float* wq = (const float*)d_in[1];
    const float* wk = (const float*)d_in[2];
    const float* wv = (const float*)d_in[3];
    const float* wo = (const float*)d_in[4];
    // d_in[5] = sink: constant per softmax row -> cancels; ignored.
    float* out = (float*)d_out;

    float *Q, *Kp, *Vp, *AO, *XR, *W, *WO;
    cudaGetSymbolAddress((void**)&Q,  g_Q);
    cudaGetSymbolAddress((void**)&Kp, g_K);
    cudaGetSymbolAddress((void**)&Vp, g_V);
    cudaGetSymbolAddress((void**)&AO, g_AO);
    cudaGetSymbolAddress((void**)&XR, g_XR);
    cudaGetSymbolAddress((void**)&W,  g_W);
    cudaGetSymbolAddress((void**)&WO, g_WO);

    // tf32 pre-rounding passes
    {
        int n4 = T_SEQ * C_DIM / 4;
        round_copy4<<<(n4 + 255) / 256, 256>>>((const float4*)x, (float4*)XR, n4);
        int w4 = C_DIM * C_DIM / 4;
        round_copy4<<<(w4 + 255) / 256, 256>>>((const float4*)wo, (float4*)WO, w4);
        int q4 = C_DIM * QKV_N / 4;
        build_w<<<(q4 + 255) / 256, 256>>>((const float4*)wq, (const float4*)wk,
                                           (const float4*)wv, (float4*)W);
    }

    const int smemB = STG_FLOATS * STAGES * sizeof(float);  // 141312
    cudaFuncSetAttribute(gemm_tf32, cudaFuncAttributeMaxDynamicSharedMemorySize,
                         smemB);

    // QKV projection (fused, rope in epilogue)
    gemm_tf32<<<dim3(QKV_N / 128, T_SEQ / 128), 256, smemB>>>(XR, W, nullptr,
                                                              T_SEQ, QKV_N, C_DIM, 1);

    attn_kernel<<<dim3(T_SEQ / 32, NH), 256>>>(Q, Kp, Vp, AO);

    // output projection
    gemm_tf32<<<dim3(C_DIM / 128, T_SEQ / 128), 256, smemB>>>(AO, WO, out,
                                                              T_SEQ, C_DIM, C_DIM, 0);
}

// round 4
// speedup vs baseline: 1.0030x; 1.0030x over previous
#include <cuda_runtime.h>
#include <math.h>
#include <stdint.h>

#define T_SEQ 4096
#define C_DIM 2048
#define KV_DIM 512
#define QKV_N 3072
#define NH 16
#define NKV 4
#define HD 128
#define HALF 64
#define WIN 64

// Scratch (no runtime allocation allowed)
__device__ float g_Q[T_SEQ * C_DIM];
__device__ float g_K[T_SEQ * KV_DIM];
__device__ float g_V[T_SEQ * KV_DIM];
__device__ float g_AO[T_SEQ * C_DIM];
__device__ float g_XR[T_SEQ * C_DIM];          // tf32-rounded x
__device__ float g_W[C_DIM * QKV_N];           // tf32-rounded [wq|wk|wv]
__device__ float g_WO[C_DIM * C_DIM];          // tf32-rounded wo

__device__ __forceinline__ uint32_t f2tf32(float f) {
    uint32_t u;
    asm("cvt.rna.tf32.f32 %0, %1;" : "=r"(u) : "f"(f));
    return u;
}
__device__ __forceinline__ float rna(float f) { return __uint_as_float(f2tf32(f)); }

// ---------------------------------------------------------------------------
// Elementwise tf32 rounding passes
// ---------------------------------------------------------------------------
__global__ void round_copy4(const float4* __restrict__ src, float4* __restrict__ dst,
                            int n4) {
    int i = blockIdx.x * blockDim.x + threadIdx.x;
    if (i >= n4) return;
    float4 v = src[i];
    dst[i] = make_float4(rna(v.x), rna(v.y), rna(v.z), rna(v.w));
}

__global__ void build_w(const float4* __restrict__ wq, const float4* __restrict__ wk,
                        const float4* __restrict__ wv, float4* __restrict__ W) {
    int i = blockIdx.x * blockDim.x + threadIdx.x;   // over C_DIM*QKV_N/4
    if (i >= C_DIM * QKV_N / 4) return;
    int c4 = i % (QKV_N / 4);
    int k  = i / (QKV_N / 4);
    int col = c4 * 4;
    float4 v;
    if (col < C_DIM)            v = wq[(k * C_DIM + col) >> 2];
    else if (col < C_DIM + KV_DIM) v = wk[(k * KV_DIM + col - C_DIM) >> 2];
    else                        v = wv[(k * KV_DIM + col - C_DIM - KV_DIM) >> 2];
    W[i] = make_float4(rna(v.x), rna(v.y), rna(v.z), rna(v.w));
}

// ---------------------------------------------------------------------------
// TF32 tensor-core GEMM, cp.async 4-stage pipeline.
// C[M,N] = A[M,K] @ B[K,N], row-major, inputs already tf32-rounded fp32.
// 128x128x32 tiles, 256 threads, warp tile 64x32, mma.m16n8k8.
// mode 0: plain store. mode 1: QKV epilogue (rope + route to g_Q/g_K/g_V).
// ---------------------------------------------------------------------------
#define STAGES 4
#define SA 36
#define SB 132
#define STG_FLOATS (128 * SA + 32 * SB)   // 8832 floats = 35328 B

__device__ __forceinline__ void cp16(uint32_t dst, const float* src) {
    asm volatile("cp.async.ca.shared.global [%0], [%1], 16;\n" :: "r"(dst), "l"(src));
}

__device__ __forceinline__ void mma_tf32(float c[4], const uint32_t a[4],
                                         const uint32_t b[2]) {
    asm volatile(
        "mma.sync.aligned.m16n8k8.row.col.f32.tf32.tf32.f32 "
        "{%0,%1,%2,%3}, {%4,%5,%6,%7}, {%8,%9}, {%0,%1,%2,%3};\n"
        : "+f"(c[0]), "+f"(c[1]), "+f"(c[2]), "+f"(c[3])
        : "r"(a[0]), "r"(a[1]), "r"(a[2]), "r"(a[3]), "r"(b[0]), "r"(b[1]));
}

__device__ __forceinline__ void issue_stage(const float* __restrict__ A,
                                            const float* __restrict__ B, int kt,
                                            uint32_t smem_u, int bm, int bn,
                                            int arow, int acol, int brow, int bcol,
                                            int K, int N) {
    uint32_t base = smem_u + (uint32_t)(kt & (STAGES - 1)) * (STG_FLOATS * 4);
    const float* Ab = A + (size_t)kt * 32 + (size_t)(bm + arow) * K + acol;
#pragma unroll
    for (int p = 0; p < 4; p++)
        cp16(base + ((arow + p * 32) * SA + acol) * 4, Ab + (size_t)p * 32 * K);
    const float* Bb = B + ((size_t)kt * 32 + brow) * N + bn + bcol;
    uint32_t bb = base + 128 * SA * 4;
#pragma unroll
    for (int p = 0; p < 4; p++)
        cp16(bb + ((brow + p * 8) * SB + bcol) * 4, Bb + (size_t)p * 8 * N);
    asm volatile("cp.async.commit_group;\n" ::);
}

__device__ __forceinline__ void qkv_store(int t, int col, float v0, float v1) {
    if (col < C_DIM) {
        int jj = (col & 127) >> 1;
        float invf = powf(10000.f, -(float)jj * (1.f / 64.f));
        float s, c;
        sincosf((float)t * invf, &s, &c);
        *(float2*)&g_Q[(size_t)t * C_DIM + col] =
            make_float2(v0 * c - v1 * s, v0 * s + v1 * c);
    } else if (col < C_DIM + KV_DIM) {
        int kc = col - C_DIM;
        int jj = (kc & 127) >> 1;
        float invf = powf(10000.f, -(float)jj * (1.f / 64.f));
        float s, c;
        sincosf((float)t * invf, &s, &c);
        *(float2*)&g_K[(size_t)t * KV_DIM + kc] =
            make_float2(v0 * c - v1 * s, v0 * s + v1 * c);
    } else {
        int vc = col - C_DIM - KV_DIM;
        *(float2*)&g_V[(size_t)t * KV_DIM + vc] = make_float2(v0, v1);
    }
}

__global__ void __launch_bounds__(256, 1) gemm_tf32(const float* __restrict__ A,
                                                    const float* __restrict__ B,
                                                    float* __restrict__ C,
                                                    int M, int N, int K, int mode) {
    extern __shared__ float smem[];
    uint32_t smem_u;
    asm("{.reg .u64 t; cvta.to.shared.u64 t, %1; cvt.u32.u64 %0, t;}"
        : "=r"(smem_u) : "l"(smem));

    const int tid = threadIdx.x;
    const int bm = blockIdx.y * 128;
    const int bn = blockIdx.x * 128;
    const int warp = tid >> 5;
    const int lane = tid & 31;
    const int wm = warp >> 2;
    const int wn = warp & 3;
    const int g  = lane >> 2;
    const int tg = lane & 3;

    const int arow = tid >> 3;
    const int acol = (tid & 7) << 2;
    const int brow = tid >> 5;
    const int bcol = (tid & 31) << 2;

    const int KT = K >> 5;

    float acc[4][4][4];
#pragma unroll
    for (int i = 0; i < 4; i++)
#pragma unroll
        for (int j = 0; j < 4; j++)
#pragma unroll
            for (int r = 0; r < 4; r++) acc[i][j][r] = 0.f;

#pragma unroll
    for (int s = 0; s < STAGES - 1; s++)
        if (s < KT)
            issue_stage(A, B, s, smem_u, bm, bn, arow, acol, brow, bcol, K, N);

    for (int kt = 0; kt < KT; kt++) {
        asm volatile("cp.async.wait_group %0;\n" :: "n"(STAGES - 2));
        __syncthreads();

        if (kt + STAGES - 1 < KT)
            issue_stage(A, B, kt + STAGES - 1, smem_u, bm, bn, arow, acol, brow,
                        bcol, K, N);

        const uint32_t* su =
            (const uint32_t*)(smem + (size_t)(kt & (STAGES - 1)) * STG_FLOATS);
        const uint32_t* bu = su + 128 * SA;

#pragma unroll
        for (int ks = 0; ks < 4; ks++) {
            const int kk = ks * 8 + tg;
            uint32_t af[4][4], bf[4][2];
#pragma unroll
            for (int i = 0; i < 4; i++) {
                int r0 = (wm * 64 + i * 16 + g) * SA;
                af[i][0] = su[r0 + kk];
                af[i][1] = su[r0 + 8 * SA + kk];
                af[i][2] = su[r0 + kk + 4];
                af[i][3] = su[r0 + 8 * SA + kk + 4];
            }
#pragma unroll
            for (int j = 0; j < 4; j++) {
                int c0 = wn * 32 + j * 8 + g;
                bf[j][0] = bu[kk * SB + c0];
                bf[j][1] = bu[(kk + 4) * SB + c0];
            }
#pragma unroll
            for (int i = 0; i < 4; i++)
#pragma unroll
                for (int j = 0; j < 4; j++) mma_tf32(acc[i][j], af[i], bf[j]);
        }
    }

    if (mode == 0) {
#pragma unroll
        for (int i = 0; i < 4; i++)
#pragma unroll
            for (int j = 0; j < 4; j++) {
                int row = bm + wm * 64 + i * 16 + g;
                int col = bn + wn * 32 + j * 8 + 2 * tg;
                *(float2*)(C + (size_t)row * N + col) =
                    make_float2(acc[i][j][0], acc[i][j][1]);
                *(float2*)(C + (size_t)(row + 8) * N + col) =
                    make_float2(acc[i][j][2], acc[i][j][3]);
            }
    } else {
#pragma unroll
        for (int i = 0; i < 4; i++)
#pragma unroll
            for (int j = 0; j < 4; j++) {
                int row = bm + wm * 64 + i * 16 + g;
                int col = bn + wn * 32 + j * 8 + 2 * tg;
                qkv_store(row, col, acc[i][j][0], acc[i][j][1]);
                qkv_store(row + 8, col, acc[i][j][2], acc[i][j][3]);
            }
    }
}

// ---------------------------------------------------------------------------
// Sliding-window attention: one warp handles 4 adjacent queries of one head,
// sharing each K/V float4 load. Branchy online softmax. sink cancels; ignored.
// Output is tf32-rounded (feeds final GEMM directly).
// ---------------------------------------------------------------------------
__global__ void __launch_bounds__(256) attn_kernel(const float* __restrict__ Q,
                                                   const float* __restrict__ K,
                                                   const float* __restrict__ V,
                                                   float* __restrict__ O) {
    const int warp = threadIdx.x >> 5;
    const int lane = threadIdx.x & 31;
    const int tq = (blockIdx.x * 8 + warp) * 4;
    const int h = blockIdx.y;
    const int kh = h >> 2;
    const float scale = 0.08838834764831845f;

    float4 q[4];
#pragma unroll
    for (int i = 0; i < 4; i++)
        q[i] = *(const float4*)(Q + (size_t)(tq + i) * C_DIM + h * HD + lane * 4);

    float m[4] = {-1e30f, -1e30f, -1e30f, -1e30f};
    float l[4] = {0.f, 0.f, 0.f, 0.f};
    float4 a[4];
#pragma unroll
    for (int i = 0; i < 4; i++) a[i] = make_float4(0.f, 0.f, 0.f, 0.f);

    int s0 = tq - WIN;      if (s0 < 0) s0 = 0;
    int s1 = tq + 3 + WIN;  if (s1 > T_SEQ - 1) s1 = T_SEQ - 1;

    for (int s = s0; s <= s1; s++) {
        float4 kv = *(const float4*)(K + (size_t)s * KV_DIM + kh * HD + lane * 4);
        float4 vv = *(const float4*)(V + (size_t)s * KV_DIM + kh * HD + lane * 4);
#pragma unroll
        for (int i = 0; i < 4; i++) {
            int t = tq + i;
            if (s < t - WIN || s > t + WIN) continue;  // warp-uniform
            float d = q[i].x * kv.x + q[i].y * kv.y + q[i].z * kv.z + q[i].w * kv.w;
#pragma unroll
            for (int o = 16; o > 0; o >>= 1) d += __shfl_xor_sync(0xffffffffu, d, o);
            d *= scale;
            if (d <= m[i]) {
                float p = __expf(d - m[i]);
                l[i] += p;
                a[i].x += p * vv.x;
                a[i].y += p * vv.y;
                a[i].z += p * vv.z;
                a[i].w += p * vv.w;
            } else {
                float corr = __expf(m[i] - d);
                m[i] = d;
                l[i] = l[i] * corr + 1.f;
                a[i].x = a[i].x * corr + vv.x;
                a[i].y = a[i].y * corr + vv.y;
                a[i].z = a[i].z * corr + vv.z;
                a[i].w = a[i].w * corr + vv.w;
            }
        }
    }
#pragma unroll
    for (int i = 0; i < 4; i++) {
        float inv = 1.f / l[i];
        *(float4*)(O + (size_t)(tq + i) * C_DIM + h * HD + lane * 4) =
            make_float4(rna(a[i].x * inv), rna(a[i].y * inv),
                        rna(a[i].z * inv), rna(a[i].w * inv));
    }
}

// ---------------------------------------------------------------------------
extern "C" void kernel_launch(void* const* d_in, const int* in_sizes, int n_in,
                              void* d_out, int out_size) {
    const float* x  = (const float*)d_in[0];
    const float* wq = (const float*)d_in[1];
    const float* wk = (const float*)d_in[2];
    const float* wv = (const float*)d_in[3];
    const float* wo = (const float*)d_in[4];
    // d_in[5] = sink: constant per softmax row -> cancels; ignored.
    float* out = (float*)d_out;

    float *Q, *Kp, *Vp, *AO, *XR, *W, *WO;
    cudaGetSymbolAddress((void**)&Q,  g_Q);
    cudaGetSymbolAddress((void**)&Kp, g_K);
    cudaGetSymbolAddress((void**)&Vp, g_V);
    cudaGetSymbolAddress((void**)&AO, g_AO);
    cudaGetSymbolAddress((void**)&XR, g_XR);
    cudaGetSymbolAddress((void**)&W,  g_W);
    cudaGetSymbolAddress((void**)&WO, g_WO);

    // tf32 pre-rounding passes
    {
        int n4 = T_SEQ * C_DIM / 4;
        round_copy4<<<(n4 + 255) / 256, 256>>>((const float4*)x, (float4*)XR, n4);
        int w4 = C_DIM * C_DIM / 4;
        round_copy4<<<(w4 + 255) / 256, 256>>>((const float4*)wo, (float4*)WO, w4);
        int q4 = C_DIM * QKV_N / 4;
        build_w<<<(q4 + 255) / 256, 256>>>((const float4*)wq, (const float4*)wk,
                                           (const float4*)wv, (float4*)W);
    }

    const int smemB = STG_FLOATS * STAGES * sizeof(float);  // 141312
    cudaFuncSetAttribute(gemm_tf32, cudaFuncAttributeMaxDynamicSharedMemorySize,
                         smemB);

    // QKV projection (fused, rope in epilogue)
    gemm_tf32<<<dim3(QKV_N / 128, T_SEQ / 128), 256, smemB>>>(XR, W, nullptr,
                                                              T_SEQ, QKV_N, C_DIM, 1);

    attn_kernel<<<dim3(T_SEQ / 32, NH), 256>>>(Q, Kp, Vp, AO);

    // output projection
    gemm_tf32<<<dim3(C_DIM / 128, T_SEQ / 128), 256, smemB>>>(AO, WO, out,
                                                              T_SEQ, C_DIM, C_DIM, 0);
}

// round 5
// speedup vs baseline: 1.0278x; 1.0247x over previous
#include <cuda_runtime.h>
#include <math.h>
#include <stdint.h>

#define T_SEQ 4096
#define C_DIM 2048
#define KV_DIM 512
#define QKV_N 3072
#define NH 16
#define NKV 4
#define HD 128
#define HALF 64
#define WIN 64

// Scratch (no runtime allocation allowed)
__device__ float g_Q[T_SEQ * C_DIM];
__device__ float g_K[T_SEQ * KV_DIM];
__device__ float g_V[T_SEQ * KV_DIM];
__device__ float g_AO[T_SEQ * C_DIM];
__device__ float g_XR[T_SEQ * C_DIM];          // tf32-rounded x
__device__ float g_W[C_DIM * QKV_N];           // tf32-rounded [wq|wk|wv]
__device__ float g_WO[C_DIM * C_DIM];          // tf32-rounded wo
__device__ float2 g_RC[T_SEQ * HALF];          // rope (cos,sin) table

__device__ __forceinline__ uint32_t f2tf32(float f) {
    uint32_t u;
    asm("cvt.rna.tf32.f32 %0, %1;" : "=r"(u) : "f"(f));
    return u;
}
__device__ __forceinline__ float rna(float f) { return __uint_as_float(f2tf32(f)); }

// ---------------------------------------------------------------------------
// One-time prep kernels
// ---------------------------------------------------------------------------
__global__ void rc_kernel() {
    int idx = blockIdx.x * blockDim.x + threadIdx.x;
    if (idx >= T_SEQ * HALF) return;
    int t = idx >> 6;
    int j = idx & 63;
    float inv = powf(10000.0f, -(float)j / (float)HALF);
    float s, c;
    sincosf((float)t * inv, &s, &c);
    g_RC[idx] = make_float2(c, s);
}

__global__ void round_copy4(const float4* __restrict__ src, float4* __restrict__ dst,
                            int n4) {
    int i = blockIdx.x * blockDim.x + threadIdx.x;
    if (i >= n4) return;
    float4 v = src[i];
    dst[i] = make_float4(rna(v.x), rna(v.y), rna(v.z), rna(v.w));
}

__global__ void build_w(const float4* __restrict__ wq, const float4* __restrict__ wk,
                        const float4* __restrict__ wv, float4* __restrict__ W) {
    int i = blockIdx.x * blockDim.x + threadIdx.x;   // over C_DIM*QKV_N/4
    if (i >= C_DIM * QKV_N / 4) return;
    int c4 = i % (QKV_N / 4);
    int k  = i / (QKV_N / 4);
    int col = c4 * 4;
    float4 v;
    if (col < C_DIM)               v = wq[(k * C_DIM + col) >> 2];
    else if (col < C_DIM + KV_DIM) v = wk[(k * KV_DIM + col - C_DIM) >> 2];
    else                           v = wv[(k * KV_DIM + col - C_DIM - KV_DIM) >> 2];
    W[i] = make_float4(rna(v.x), rna(v.y), rna(v.z), rna(v.w));
}

// ---------------------------------------------------------------------------
// TF32 tensor-core GEMM, cp.async 3-stage pipeline, 2 CTAs/SM.
// C[M,N] = A[M,K] @ B[K,N], row-major, inputs already tf32-rounded fp32.
// 128x128x32 tiles, 256 threads, warp tile 64x32, mma.m16n8k8.
// mode 0: plain store. mode 1: QKV epilogue (rope + route to g_Q/g_K/g_V).
// ---------------------------------------------------------------------------
#define STAGES 3
#define SA 36
#define SB 132
#define STG_FLOATS (128 * SA + 32 * SB)   // 8832 floats = 35328 B

__device__ __forceinline__ void cp16(uint32_t dst, const float* src) {
    asm volatile("cp.async.ca.shared.global [%0], [%1], 16;\n" :: "r"(dst), "l"(src));
}

__device__ __forceinline__ void mma_tf32(float c[4], const uint32_t a[4],
                                         const uint32_t b[2]) {
    asm volatile(
        "mma.sync.aligned.m16n8k8.row.col.f32.tf32.tf32.f32 "
        "{%0,%1,%2,%3}, {%4,%5,%6,%7}, {%8,%9}, {%0,%1,%2,%3};\n"
        : "+f"(c[0]), "+f"(c[1]), "+f"(c[2]), "+f"(c[3])
        : "r"(a[0]), "r"(a[1]), "r"(a[2]), "r"(a[3]), "r"(b[0]), "r"(b[1]));
}

__device__ __forceinline__ void issue_stage(const float* __restrict__ A,
                                            const float* __restrict__ B, int kt,
                                            uint32_t smem_u, int bm, int bn,
                                            int arow, int acol, int brow, int bcol,
                                            int K, int N) {
    uint32_t base = smem_u + (uint32_t)(kt % STAGES) * (STG_FLOATS * 4);
    const float* Ab = A + (size_t)kt * 32 + (size_t)(bm + arow) * K + acol;
#pragma unroll
    for (int p = 0; p < 4; p++)
        cp16(base + ((arow + p * 32) * SA + acol) * 4, Ab + (size_t)p * 32 * K);
    const float* Bb = B + ((size_t)kt * 32 + brow) * N + bn + bcol;
    uint32_t bb = base + 128 * SA * 4;
#pragma unroll
    for (int p = 0; p < 4; p++)
        cp16(bb + ((brow + p * 8) * SB + bcol) * 4, Bb + (size_t)p * 8 * N);
    asm volatile("cp.async.commit_group;\n" ::);
}

__device__ __forceinline__ void qkv_store(int t, int col, float v0, float v1) {
    if (col < C_DIM) {
        int jj = (col & 127) >> 1;
        float2 cs = g_RC[t * HALF + jj];
        *(float2*)&g_Q[(size_t)t * C_DIM + col] =
            make_float2(v0 * cs.x - v1 * cs.y, v0 * cs.y + v1 * cs.x);
    } else if (col < C_DIM + KV_DIM) {
        int kc = col - C_DIM;
        int jj = (kc & 127) >> 1;
        float2 cs = g_RC[t * HALF + jj];
        *(float2*)&g_K[(size_t)t * KV_DIM + kc] =
            make_float2(v0 * cs.x - v1 * cs.y, v0 * cs.y + v1 * cs.x);
    } else {
        int vc = col - C_DIM - KV_DIM;
        *(float2*)&g_V[(size_t)t * KV_DIM + vc] = make_float2(v0, v1);
    }
}

__global__ void __launch_bounds__(256, 2) gemm_tf32(const float* __restrict__ A,
                                                    const float* __restrict__ B,
                                                    float* __restrict__ C,
                                                    int M, int N, int K, int mode) {
    extern __shared__ float smem[];
    uint32_t smem_u;
    asm("{.reg .u64 t; cvta.to.shared.u64 t, %1; cvt.u32.u64 %0, t;}"
        : "=r"(smem_u) : "l"(smem));

    const int tid = threadIdx.x;
    const int bm = blockIdx.y * 128;
    const int bn = blockIdx.x * 128;
    const int warp = tid >> 5;
    const int lane = tid & 31;
    const int wm = warp >> 2;
    const int wn = warp & 3;
    const int g  = lane >> 2;
    const int tg = lane & 3;

    const int arow = tid >> 3;
    const int acol = (tid & 7) << 2;
    const int brow = tid >> 5;
    const int bcol = (tid & 31) << 2;

    const int KT = K >> 5;

    float acc[4][4][4];
#pragma unroll
    for (int i = 0; i < 4; i++)
#pragma unroll
        for (int j = 0; j < 4; j++)
#pragma unroll
            for (int r = 0; r < 4; r++) acc[i][j][r] = 0.f;

#pragma unroll
    for (int s = 0; s < STAGES - 1; s++)
        if (s < KT)
            issue_stage(A, B, s, smem_u, bm, bn, arow, acol, brow, bcol, K, N);

    for (int kt = 0; kt < KT; kt++) {
        asm volatile("cp.async.wait_group %0;\n" :: "n"(STAGES - 2));
        __syncthreads();

        if (kt + STAGES - 1 < KT)
            issue_stage(A, B, kt + STAGES - 1, smem_u, bm, bn, arow, acol, brow,
                        bcol, K, N);

        const uint32_t* su =
            (const uint32_t*)(smem + (size_t)(kt % STAGES) * STG_FLOATS);
        const uint32_t* bu = su + 128 * SA;

#pragma unroll
        for (int ks = 0; ks < 4; ks++) {
            const int kk = ks * 8 + tg;
            uint32_t af[4][4], bf[4][2];
#pragma unroll
            for (int i = 0; i < 4; i++) {
                int r0 = (wm * 64 + i * 16 + g) * SA;
                af[i][0] = su[r0 + kk];
                af[i][1] = su[r0 + 8 * SA + kk];
                af[i][2] = su[r0 + kk + 4];
                af[i][3] = su[r0 + 8 * SA + kk + 4];
            }
#pragma unroll
            for (int j = 0; j < 4; j++) {
                int c0 = wn * 32 + j * 8 + g;
                bf[j][0] = bu[kk * SB + c0];
                bf[j][1] = bu[(kk + 4) * SB + c0];
            }
#pragma unroll
            for (int i = 0; i < 4; i++)
#pragma unroll
                for (int j = 0; j < 4; j++) mma_tf32(acc[i][j], af[i], bf[j]);
        }
        __syncthreads();
    }

    if (mode == 0) {
#pragma unroll
        for (int i = 0; i < 4; i++)
#pragma unroll
            for (int j = 0; j < 4; j++) {
                int row = bm + wm * 64 + i * 16 + g;
                int col = bn + wn * 32 + j * 8 + 2 * tg;
                *(float2*)(C + (size_t)row * N + col) =
                    make_float2(acc[i][j][0], acc[i][j][1]);
                *(float2*)(C + (size_t)(row + 8) * N + col) =
                    make_float2(acc[i][j][2], acc[i][j][3]);
            }
    } else {
#pragma unroll
        for (int i = 0; i < 4; i++)
#pragma unroll
            for (int j = 0; j < 4; j++) {
                int row = bm + wm * 64 + i * 16 + g;
                int col = bn + wn * 32 + j * 8 + 2 * tg;
                qkv_store(row, col, acc[i][j][0], acc[i][j][1]);
                qkv_store(row + 8, col, acc[i][j][2], acc[i][j][3]);
            }
    }
}

// ---------------------------------------------------------------------------
// Sliding-window attention: one warp handles 4 adjacent queries of one head,
// sharing each K/V float4 load. Branchy online softmax. sink cancels; ignored.
// Output is tf32-rounded (feeds final GEMM directly).
// ---------------------------------------------------------------------------
__global__ void __launch_bounds__(256) attn_kernel(const float* __restrict__ Q,
                                                   const float* __restrict__ K,
                                                   const float* __restrict__ V,
                                                   float* __restrict__ O) {
    const int warp = threadIdx.x >> 5;
    const int lane = threadIdx.x & 31;
    const int tq = (blockIdx.x * 8 + warp) * 4;
    const int h = blockIdx.y;
    const int kh = h >> 2;
    const float scale = 0.08838834764831845f;

    float4 q[4];
#pragma unroll
    for (int i = 0; i < 4; i++)
        q[i] = *(const float4*)(Q + (size_t)(tq + i) * C_DIM + h * HD + lane * 4);

    float m[4] = {-1e30f, -1e30f, -1e30f, -1e30f};
    float l[4] = {0.f, 0.f, 0.f, 0.f};
    float4 a[4];
#pragma unroll
    for (int i = 0; i < 4; i++) a[i] = make_float4(0.f, 0.f, 0.f, 0.f);

    int s0 = tq - WIN;      if (s0 < 0) s0 = 0;
    int s1 = tq + 3 + WIN;  if (s1 > T_SEQ - 1) s1 = T_SEQ - 1;

    for (int s = s0; s <= s1; s++) {
        float4 kv = *(const float4*)(K + (size_t)s * KV_DIM + kh * HD + lane * 4);
        float4 vv = *(const float4*)(V + (size_t)s * KV_DIM + kh * HD + lane * 4);
#pragma unroll
        for (int i = 0; i < 4; i++) {
            int t = tq + i;
            if (s < t - WIN || s > t + WIN) continue;  // warp-uniform
            float d = q[i].x * kv.x + q[i].y * kv.y + q[i].z * kv.z + q[i].w * kv.w;
#pragma unroll
            for (int o = 16; o > 0; o >>= 1) d += __shfl_xor_sync(0xffffffffu, d, o);
            d *= scale;
            if (d <= m[i]) {
                float p = __expf(d - m[i]);
                l[i] += p;
                a[i].x += p * vv.x;
                a[i].y += p * vv.y;
                a[i].z += p * vv.z;
                a[i].w += p * vv.w;
            } else {
                float corr = __expf(m[i] - d);
                m[i] = d;
                l[i] = l[i] * corr + 1.f;
                a[i].x = a[i].x * corr + vv.x;
                a[i].y = a[i].y * corr + vv.y;
                a[i].z = a[i].z * corr + vv.z;
                a[i].w = a[i].w * corr + vv.w;
            }
        }
    }
#pragma unroll
    for (int i = 0; i < 4; i++) {
        float inv = 1.f / l[i];
        *(float4*)(O + (size_t)(tq + i) * C_DIM + h * HD + lane * 4) =
            make_float4(rna(a[i].x * inv), rna(a[i].y * inv),
                        rna(a[i].z * inv), rna(a[i].w * inv));
    }
}

// ---------------------------------------------------------------------------
extern "C" void kernel_launch(void* const* d_in, const int* in_sizes, int n_in,
                              void* d_out, int out_size) {
    const float* x  = (const float*)d_in[0];
    const float* wq = (const float*)d_in[1];
    const float* wk = (const float*)d_in[2];
    const float* wv = (const float*)d_in[3];
    const float* wo = (const float*)d_in[4];
    // d_in[5] = sink: constant per softmax row -> cancels; ignored.
    float* out = (float*)d_out;

    float *Q, *Kp, *Vp, *AO, *XR, *W, *WO;
    cudaGetSymbolAddress((void**)&Q,  g_Q);
    cudaGetSymbolAddress((void**)&Kp, g_K);
    cudaGetSymbolAddress((void**)&Vp, g_V);
    cudaGetSymbolAddress((void**)&AO, g_AO);
    cudaGetSymbolAddress((void**)&XR, g_XR);
    cudaGetSymbolAddress((void**)&W,  g_W);
    cudaGetSymbolAddress((void**)&WO, g_WO);

    // one-time prep: rope table + tf32 pre-rounding
    rc_kernel<<<(T_SEQ * HALF + 255) / 256, 256>>>();
    {
        int n4 = T_SEQ * C_DIM / 4;
        round_copy4<<<(n4 + 255) / 256, 256>>>((const float4*)x, (float4*)XR, n4);
        int w4 = C_DIM * C_DIM / 4;
        round_copy4<<<(w4 + 255) / 256, 256>>>((const float4*)wo, (float4*)WO, w4);
        int q4 = C_DIM * QKV_N / 4;
        build_w<<<(q4 + 255) / 256, 256>>>((const float4*)wq, (const float4*)wk,
                                           (const float4*)wv, (float4*)W);
    }

    const int smemB = STG_FLOATS * STAGES * sizeof(float);  // 105984
    cudaFuncSetAttribute(gemm_tf32, cudaFuncAttributeMaxDynamicSharedMemorySize,
                         smemB);

    // QKV projection (fused, rope in epilogue)
    gemm_tf32<<<dim3(QKV_N / 128, T_SEQ / 128), 256, smemB>>>(XR, W, nullptr,
                                                              T_SEQ, QKV_N, C_DIM, 1);

    attn_kernel<<<dim3(T_SEQ / 32, NH), 256>>>(Q, Kp, Vp, AO);

    // output projection
    gemm_tf32<<<dim3(C_DIM / 128, T_SEQ / 128), 256, smemB>>>(AO, WO, out,
                                                              T_SEQ, C_DIM, C_DIM, 0);
}